// round 11
// baseline (speedup 1.0000x reference)
#include <cuda_runtime.h>
#include <cuda_fp16.h>
#include <cstdint>

// Problem constants
#define NROWS   500000
#define KCODES  512
#define DDIM    64
#define TILE_M  384
#define NTHREADS 768
#define NUMTILES ((NROWS + TILE_M - 1) / TILE_M)   // 1303

// Shared memory layout (byte offsets into dynamic smem)
#define SMEM_B_HI   0            // 512 x 128B fp16 (-2*e), SW128-swizzled
#define SMEM_ESQ    65536        // 512 floats (||e_k||^2)
#define SMEM_IDX    67584        // 384 rows x 32B (4 threads x int2 candidates)
#define SMEM_WIN    79872        // 384 int (winner per row)
#define SMEM_TOTAL  81408

__device__ __forceinline__ uint32_t smem_u32(const void* p) {
    uint32_t a;
    asm("{ .reg .u64 t; cvta.to.shared.u64 t, %1; cvt.u32.u64 %0, t; }" : "=r"(a) : "l"(p));
    return a;
}
__device__ __forceinline__ uint32_t swz(uint32_t bo) { return bo ^ ((bo >> 3) & 0x70); }

__device__ __forceinline__ void mma_f16(float* d, const uint32_t* a, const uint32_t* b) {
    asm volatile(
        "mma.sync.aligned.m16n8k16.row.col.f32.f16.f16.f32 "
        "{%0,%1,%2,%3}, {%4,%5,%6,%7}, {%8,%9}, {%0,%1,%2,%3};"
        : "+f"(d[0]), "+f"(d[1]), "+f"(d[2]), "+f"(d[3])
        : "r"(a[0]), "r"(a[1]), "r"(a[2]), "r"(a[3]), "r"(b[0]), "r"(b[1]));
}
__device__ __forceinline__ void ldsm4(uint32_t* r, uint32_t addr) {
    asm volatile("ldmatrix.sync.aligned.m8n8.x4.shared.b16 {%0,%1,%2,%3}, [%4];"
        : "=r"(r[0]), "=r"(r[1]), "=r"(r[2]), "=r"(r[3]) : "r"(addr));
}

__device__ __forceinline__ uint32_t pack_h2(float2 v) {
    __half2 hh = __floats2half2_rn(v.x, v.y);
    return *reinterpret_cast<uint32_t*>(&hh);
}

__global__ void __launch_bounds__(NTHREADS, 1) vq_kernel(
    const float* __restrict__ x, const float* __restrict__ emb,
    float* __restrict__ out, int out_size)
{
    extern __shared__ char smem[];
    const uint32_t sb = smem_u32(smem);
    const int tid  = threadIdx.x;
    const int lane = tid & 31;
    const int warpRow = (tid >> 5) * 16;     // 24 warps x 16 rows = 384 rows

    // ---- Stage B = fp16(-2 * embedding), SW128; compute exact e_sq ----
    if (tid < 512) {
        int r = tid;
        const float4* src = (const float4*)(emb + (size_t)r * DDIM);
        float ssum = 0.f;
#pragma unroll
        for (int j = 0; j < 16; j += 2) {
            float4 v0 = src[j], v1 = src[j + 1];
            ssum = fmaf(v0.x, v0.x, ssum); ssum = fmaf(v0.y, v0.y, ssum);
            ssum = fmaf(v0.z, v0.z, ssum); ssum = fmaf(v0.w, v0.w, ssum);
            ssum = fmaf(v1.x, v1.x, ssum); ssum = fmaf(v1.y, v1.y, ssum);
            ssum = fmaf(v1.z, v1.z, ssum); ssum = fmaf(v1.w, v1.w, ssum);
            uint4 hi = make_uint4(
                pack_h2(make_float2(-2.f * v0.x, -2.f * v0.y)),
                pack_h2(make_float2(-2.f * v0.z, -2.f * v0.w)),
                pack_h2(make_float2(-2.f * v1.x, -2.f * v1.y)),
                pack_h2(make_float2(-2.f * v1.z, -2.f * v1.w)));
            uint32_t sw = swz((uint32_t)r * 128u + (uint32_t)(j >> 1) * 16u);
            *(uint4*)(smem + SMEM_B_HI + sw) = hi;
        }
        ((float*)(smem + SMEM_ESQ))[r] = ssum;
    }
    __syncthreads();

    // ---- Per-lane constant B addressing (swizzle algebra hoisted) ----
    const int bRow4 = (lane & 7) + ((lane >> 4) << 3);
    const int bKb4  = ((lane >> 3) & 1) << 4;
    const uint32_t laneBaseB = (uint32_t)bRow4 * 128u + (uint32_t)(bKb4 ^ ((lane & 1) << 4));
    const uint32_t kXor = (uint32_t)(lane & 6) << 4;
    uint32_t bAddrHi[4];
#pragma unroll
    for (int ks = 0; ks < 4; ks++) {
        bAddrHi[ks] = sb + SMEM_B_HI + laneBaseB + (((uint32_t)ks * 32u) ^ kXor);
    }

    const float* esq = (const float*)(smem + SMEM_ESQ);
    const int ciB = (lane & 3) * 2;

    for (int t = blockIdx.x; t < NUMTILES; t += gridDim.x) {
        const size_t base = (size_t)t * TILE_M;

        // ---- A fragments straight from global, fp16 (no residual) ----
        uint32_t ah[4][4];
        {
            const int kA = (lane & 3) * 2;
            size_t r0 = base + warpRow + (lane >> 2);
            size_t r1 = r0 + 8;
            if (r0 >= NROWS) r0 = NROWS - 1;   // clamp: garbage rows never emitted
            if (r1 >= NROWS) r1 = NROWS - 1;
            const float* p0 = x + r0 * DDIM + kA;
            const float* p1 = x + r1 * DDIM + kA;
#pragma unroll
            for (int ks = 0; ks < 4; ks++) {
                ah[ks][0] = pack_h2(*(const float2*)(p0 + ks * 16));
                ah[ks][1] = pack_h2(*(const float2*)(p1 + ks * 16));
                ah[ks][2] = pack_h2(*(const float2*)(p0 + ks * 16 + 8));
                ah[ks][3] = pack_h2(*(const float2*)(p1 + ks * 16 + 8));
            }
        }

        // ---- Per-thread top-2 trackers (tk = rowhalf); packed indices ----
        float b1[2], b2[2]; uint32_t i12[2];
#pragma unroll
        for (int k = 0; k < 2; k++) { b1[k] = 3.4e38f; b2[k] = 3.4e38f; i12[k] = 0; }

        uint32_t nbOff = 0;
        int nbBase = ciB;

#pragma unroll 1
        for (int np = 0; np < 32; np++) {
            const int nb = np * 16;
            float2 e01 = *(const float2*)(esq + nb + ciB);
            float2 e23 = *(const float2*)(esq + nb + 8 + ciB);
            float acc[2][4];
            acc[0][0] = e01.x; acc[0][1] = e01.y; acc[0][2] = e01.x; acc[0][3] = e01.y;
            acc[1][0] = e23.x; acc[1][1] = e23.y; acc[1][2] = e23.x; acc[1][3] = e23.y;

#pragma unroll
            for (int ks = 0; ks < 4; ks++) {
                uint32_t bh[4];
                ldsm4(bh, bAddrHi[ks] + nbOff);
                mma_f16(acc[0], ah[ks], bh);
                mma_f16(acc[1], ah[ks], bh + 2);
            }

            // ---- Direct top-2 update on all 4 scores per row-half (no tree:
            //      group elimination is unsafe at 1-pass accuracy) ----
#pragma unroll
            for (int h = 0; h < 2; h++) {
#pragma unroll
                for (int nt = 0; nt < 2; nt++) {
#pragma unroll
                    for (int par = 0; par < 2; par++) {
                        float m = acc[nt][h * 2 + par];
                        uint32_t ci = (uint32_t)(nbBase + nt * 8 + par);
                        if (m < b1[h]) {
                            b2[h] = b1[h];
                            i12[h] = (i12[h] << 16) | ci;
                            b1[h] = m;
                        } else if (m < b2[h]) {
                            b2[h] = m;
                            i12[h] = (i12[h] & 0xFFFFu) | (ci << 16);
                        }
                    }
                }
            }
            nbOff += 2048;
            nbBase += 16;
        }

        // ---- Every thread writes its top-2 -> 8 candidates per row ----
#pragma unroll
        for (int tk = 0; tk < 2; tk++) {
            int row = warpRow + tk * 8 + (lane >> 2);
            *(int2*)(smem + SMEM_IDX + row * 32 + (lane & 3) * 8) =
                make_int2((int)(i12[tk] & 0xFFFFu), (int)(i12[tk] >> 16));
        }
        __syncthreads();

        // ---- Exact fp32 rescore of ALL 8 candidates: 2 threads per row ----
        {
            const int row  = tid >> 1;
            const int half = tid & 1;
            const size_t g = base + row;
            if (g < (size_t)NROWS) {
                const int2* cp = (const int2*)(smem + SMEM_IDX + row * 32 + half * 16);
                int2 ca = cp[0], cb = cp[1];
                int c[4] = {ca.x, ca.y, cb.x, cb.y};
                const float4* xr = (const float4*)(x + g * DDIM);
                const float4* e0 = (const float4*)(emb + (size_t)c[0] * DDIM);
                const float4* e1 = (const float4*)(emb + (size_t)c[1] * DDIM);
                const float4* e2 = (const float4*)(emb + (size_t)c[2] * DDIM);
                const float4* e3 = (const float4*)(emb + (size_t)c[3] * DDIM);
                float d0 = 0.f, d1 = 0.f, d2 = 0.f, d3 = 0.f;
#pragma unroll
                for (int j = 0; j < 16; j++) {
                    float4 xv = xr[j];
                    float4 a = e0[j], b = e1[j], cc = e2[j], dd = e3[j];
                    float u;
                    u = xv.x - a.x;  d0 = fmaf(u, u, d0);
                    u = xv.y - a.y;  d0 = fmaf(u, u, d0);
                    u = xv.z - a.z;  d0 = fmaf(u, u, d0);
                    u = xv.w - a.w;  d0 = fmaf(u, u, d0);
                    u = xv.x - b.x;  d1 = fmaf(u, u, d1);
                    u = xv.y - b.y;  d1 = fmaf(u, u, d1);
                    u = xv.z - b.z;  d1 = fmaf(u, u, d1);
                    u = xv.w - b.w;  d1 = fmaf(u, u, d1);
                    u = xv.x - cc.x; d2 = fmaf(u, u, d2);
                    u = xv.y - cc.y; d2 = fmaf(u, u, d2);
                    u = xv.z - cc.z; d2 = fmaf(u, u, d2);
                    u = xv.w - cc.w; d2 = fmaf(u, u, d2);
                    u = xv.x - dd.x; d3 = fmaf(u, u, d3);
                    u = xv.y - dd.y; d3 = fmaf(u, u, d3);
                    u = xv.z - dd.z; d3 = fmaf(u, u, d3);
                    u = xv.w - dd.w; d3 = fmaf(u, u, d3);
                }
                // Min of my 4 with index tie-break (smallest index wins)
                float dm = d0; int im = c[0];
                if (d1 < dm || (d1 == dm && c[1] < im)) { dm = d1; im = c[1]; }
                if (d2 < dm || (d2 == dm && c[2] < im)) { dm = d2; im = c[2]; }
                if (d3 < dm || (d3 == dm && c[3] < im)) { dm = d3; im = c[3]; }
                // Merge with partner thread
                float do_ = __shfl_xor_sync(0xFFFFFFFFu, dm, 1);
                int   io_ = __shfl_xor_sync(0xFFFFFFFFu, im, 1);
                if (half == 0) {
                    int win = (do_ < dm || (do_ == dm && io_ < im)) ? io_ : im;
                    ((int*)(smem + SMEM_WIN))[row] = win;
                    if (out_size >= NROWS * DDIM + NROWS) {
                        out[(size_t)NROWS * DDIM + g] = (float)win;
                    }
                }
            }
        }
        __syncthreads();

        // ---- Gather quantized rows (8 threads per row, 32B each) ----
        if (out_size >= NROWS * DDIM) {
#pragma unroll
            for (int sweep = 0; sweep < 4; sweep++) {
                int r = sweep * 96 + (tid >> 3);
                size_t gr = base + r;
                if (r < TILE_M && gr < (size_t)NROWS) {
                    int w = ((const int*)(smem + SMEM_WIN))[r];
                    const float4* e = (const float4*)(emb + (size_t)w * DDIM) + (tid & 7) * 2;
                    float4* q = (float4*)(out + gr * DDIM) + (tid & 7) * 2;
                    q[0] = e[0]; q[1] = e[1];
                }
            }
        }
        __syncthreads();   // protect IDX/WIN before next tile
    }
}

extern "C" void kernel_launch(void* const* d_in, const int* in_sizes, int n_in,
                              void* d_out, int out_size) {
    const float* x   = (const float*)d_in[0];
    const float* emb = (const float*)d_in[1];
    float* out = (float*)d_out;
    cudaFuncSetAttribute(vq_kernel, cudaFuncAttributeMaxDynamicSharedMemorySize, SMEM_TOTAL);
    vq_kernel<<<148, NTHREADS, SMEM_TOTAL>>>(x, emb, out, out_size);
}

// round 12
// speedup vs baseline: 1.4204x; 1.4204x over previous
#include <cuda_runtime.h>
#include <cuda_fp16.h>
#include <cstdint>

// Problem constants
#define NROWS   500000
#define KCODES  512
#define DDIM    64
#define TILE_M  384
#define NTHREADS 768
#define NUMTILES ((NROWS + TILE_M - 1) / TILE_M)   // 1303

// Shared memory layout (byte offsets into dynamic smem)
#define SMEM_B      0            // 512 x 128B fp16 (-2*e), SW128-swizzled
#define SMEM_ESQ    65536        // 512 floats (||e_k||^2)
#define SMEM_EMB    67584        // 512 x 256B fp32 embedding, XOR-swizzled rows
#define SMEM_IDX    198656       // 384 rows x 32B (4 threads x int2 candidates)
#define SMEM_WIN    210944       // 384 int (winner per row)
#define SMEM_TOTAL  212480       // 207.5 KB

__device__ __forceinline__ uint32_t smem_u32(const void* p) {
    uint32_t a;
    asm("{ .reg .u64 t; cvta.to.shared.u64 t, %1; cvt.u32.u64 %0, t; }" : "=r"(a) : "l"(p));
    return a;
}
__device__ __forceinline__ uint32_t swz(uint32_t bo) { return bo ^ ((bo >> 3) & 0x70); }
// fp32 emb row c, 16-byte chunk j (0..15): bank-decorrelated via XOR swizzle
__device__ __forceinline__ uint32_t embOff(int c, int j) {
    return (uint32_t)(SMEM_EMB + c * 256 + ((j * 16) ^ ((c & 7) << 4)));
}

__device__ __forceinline__ void mma_f16(float* d, const uint32_t* a, const uint32_t* b) {
    asm volatile(
        "mma.sync.aligned.m16n8k16.row.col.f32.f16.f16.f32 "
        "{%0,%1,%2,%3}, {%4,%5,%6,%7}, {%8,%9}, {%0,%1,%2,%3};"
        : "+f"(d[0]), "+f"(d[1]), "+f"(d[2]), "+f"(d[3])
        : "r"(a[0]), "r"(a[1]), "r"(a[2]), "r"(a[3]), "r"(b[0]), "r"(b[1]));
}
__device__ __forceinline__ void ldsm4(uint32_t* r, uint32_t addr) {
    asm volatile("ldmatrix.sync.aligned.m8n8.x4.shared.b16 {%0,%1,%2,%3}, [%4];"
        : "=r"(r[0]), "=r"(r[1]), "=r"(r[2]), "=r"(r[3]) : "r"(addr));
}
__device__ __forceinline__ uint32_t pack_h2(float2 v) {
    __half2 hh = __floats2half2_rn(v.x, v.y);
    return *reinterpret_cast<uint32_t*>(&hh);
}

__global__ void __launch_bounds__(NTHREADS, 1) vq_kernel(
    const float* __restrict__ x, const float* __restrict__ emb,
    float* __restrict__ out, int out_size)
{
    extern __shared__ char smem[];
    const uint32_t sb = smem_u32(smem);
    const int tid  = threadIdx.x;
    const int lane = tid & 31;
    const int warpRow = (tid >> 5) * 16;     // 24 warps x 16 rows = 384 rows

    // ---- Stage B = fp16(-2e) SW128 + fp32 emb (swizzled) + exact e_sq ----
    if (tid < 512) {
        int r = tid;
        const float4* src = (const float4*)(emb + (size_t)r * DDIM);
        float ssum = 0.f;
#pragma unroll
        for (int j = 0; j < 16; j += 2) {
            float4 v0 = src[j], v1 = src[j + 1];
            ssum = fmaf(v0.x, v0.x, ssum); ssum = fmaf(v0.y, v0.y, ssum);
            ssum = fmaf(v0.z, v0.z, ssum); ssum = fmaf(v0.w, v0.w, ssum);
            ssum = fmaf(v1.x, v1.x, ssum); ssum = fmaf(v1.y, v1.y, ssum);
            ssum = fmaf(v1.z, v1.z, ssum); ssum = fmaf(v1.w, v1.w, ssum);
            *(float4*)(smem + embOff(r, j))     = v0;
            *(float4*)(smem + embOff(r, j + 1)) = v1;
            uint4 hi = make_uint4(
                pack_h2(make_float2(-2.f * v0.x, -2.f * v0.y)),
                pack_h2(make_float2(-2.f * v0.z, -2.f * v0.w)),
                pack_h2(make_float2(-2.f * v1.x, -2.f * v1.y)),
                pack_h2(make_float2(-2.f * v1.z, -2.f * v1.w)));
            uint32_t sw = swz((uint32_t)r * 128u + (uint32_t)(j >> 1) * 16u);
            *(uint4*)(smem + SMEM_B + sw) = hi;
        }
        ((float*)(smem + SMEM_ESQ))[r] = ssum;
    }
    __syncthreads();

    // ---- Per-lane constant B addressing (swizzle algebra hoisted) ----
    const int bRow4 = (lane & 7) + ((lane >> 4) << 3);
    const int bKb4  = ((lane >> 3) & 1) << 4;
    const uint32_t laneBaseB = (uint32_t)bRow4 * 128u + (uint32_t)(bKb4 ^ ((lane & 1) << 4));
    const uint32_t kXor = (uint32_t)(lane & 6) << 4;
    uint32_t bAddr[4];
#pragma unroll
    for (int ks = 0; ks < 4; ks++) {
        bAddr[ks] = sb + SMEM_B + laneBaseB + (((uint32_t)ks * 32u) ^ kXor);
    }

    const float* esq = (const float*)(smem + SMEM_ESQ);
    const int ciB = (lane & 3) * 2;

    for (int t = blockIdx.x; t < NUMTILES; t += gridDim.x) {
        const size_t base = (size_t)t * TILE_M;

        // ---- A fragments straight from global, fp16 ----
        uint32_t ah[4][4];
        {
            const int kA = (lane & 3) * 2;
            size_t r0 = base + warpRow + (lane >> 2);
            size_t r1 = r0 + 8;
            if (r0 >= NROWS) r0 = NROWS - 1;   // clamp: garbage rows never emitted
            if (r1 >= NROWS) r1 = NROWS - 1;
            const float* p0 = x + r0 * DDIM + kA;
            const float* p1 = x + r1 * DDIM + kA;
#pragma unroll
            for (int ks = 0; ks < 4; ks++) {
                ah[ks][0] = pack_h2(*(const float2*)(p0 + ks * 16));
                ah[ks][1] = pack_h2(*(const float2*)(p1 + ks * 16));
                ah[ks][2] = pack_h2(*(const float2*)(p0 + ks * 16 + 8));
                ah[ks][3] = pack_h2(*(const float2*)(p1 + ks * 16 + 8));
            }
        }

        // ---- Per-thread top-2 trackers (tk = rowhalf) ----
        float b1[2], b2[2]; int j1[2], j2[2];
#pragma unroll
        for (int k = 0; k < 2; k++) { b1[k] = 3.4e38f; b2[k] = 3.4e38f; j1[k] = 0; j2[k] = 0; }

        uint32_t nbOff = 0;
        int nbBase = ciB;

#pragma unroll 1
        for (int np = 0; np < 32; np++) {
            const int nb = np * 16;
            float2 e01 = *(const float2*)(esq + nb + ciB);
            float2 e23 = *(const float2*)(esq + nb + 8 + ciB);
            float acc[2][4];
            acc[0][0] = e01.x; acc[0][1] = e01.y; acc[0][2] = e01.x; acc[0][3] = e01.y;
            acc[1][0] = e23.x; acc[1][1] = e23.y; acc[1][2] = e23.x; acc[1][3] = e23.y;

#pragma unroll
            for (int ks = 0; ks < 4; ks++) {
                uint32_t bh[4];
                ldsm4(bh, bAddr[ks] + nbOff);
                mma_f16(acc[0], ah[ks], bh);
                mma_f16(acc[1], ah[ks], bh + 2);
            }

            // ---- Branchless epilogue: exact top-2-of-4 network + sorted merge
            //      (select chains, no predicated-guard serialization) ----
#pragma unroll
            for (int h = 0; h < 2; h++) {
                float s0 = acc[0][h * 2], s1 = acc[0][h * 2 + 1];
                float s2 = acc[1][h * 2], s3 = acc[1][h * 2 + 1];
                int x0 = nbBase, x1 = nbBase + 1, x2 = nbBase + 8, x3 = nbBase + 9;
                // pairwise sort
                bool c01 = s1 < s0;
                float lo1 = c01 ? s1 : s0, hi1 = c01 ? s0 : s1;
                int   la  = c01 ? x1 : x0, ha  = c01 ? x0 : x1;
                bool c23 = s3 < s2;
                float lo2 = c23 ? s3 : s2, hi2 = c23 ? s2 : s3;
                int   lb  = c23 ? x3 : x2, hb  = c23 ? x2 : x3;
                // top-2 of 4
                bool cl = lo2 < lo1;
                float m1 = cl ? lo2 : lo1;  int mi1 = cl ? lb : la;
                float tt = cl ? lo1 : lo2;  int tti = cl ? la : lb;
                bool ch = hi2 < hi1;
                float uu = ch ? hi2 : hi1;  int uui = ch ? hb : ha;
                bool cm = uu < tt;
                float m2 = cm ? uu : tt;    int mi2 = cm ? uui : tti;
                // merge sorted (m1,m2) into sorted (b1,b2)
                bool d1 = m1 < b1[h];
                float nb1 = d1 ? m1 : b1[h]; int ni1 = d1 ? mi1 : j1[h];
                float ls  = d1 ? b1[h] : m1; int li  = d1 ? j1[h] : mi1;
                bool d2 = m2 < b2[h];
                float rs = d2 ? m2 : b2[h];  int ri  = d2 ? mi2 : j2[h];
                bool d3 = ls < rs;
                b2[h] = d3 ? ls : rs;        j2[h] = d3 ? li : ri;
                b1[h] = nb1;                 j1[h] = ni1;
            }
            nbOff += 2048;
            nbBase += 16;
        }

        // ---- Every thread writes its top-2 -> 8 candidates per row ----
#pragma unroll
        for (int tk = 0; tk < 2; tk++) {
            int row = warpRow + tk * 8 + (lane >> 2);
            *(int2*)(smem + SMEM_IDX + row * 32 + (lane & 3) * 8) = make_int2(j1[tk], j2[tk]);
        }
        __syncthreads();

        // ---- Exact fp32 rescore of ALL 8 candidates (emb from smem) ----
        {
            const int row  = tid >> 1;
            const int half = tid & 1;
            const size_t g = base + row;
            if (g < (size_t)NROWS) {
                const int2* cp = (const int2*)(smem + SMEM_IDX + row * 32 + half * 16);
                int2 ca = cp[0], cb = cp[1];
                int c[4] = {ca.x, ca.y, cb.x, cb.y};
                const float4* xr = (const float4*)(x + g * DDIM);
                float d0 = 0.f, d1 = 0.f, d2 = 0.f, d3 = 0.f;
#pragma unroll
                for (int j = 0; j < 16; j++) {
                    float4 xv = xr[j];
                    float4 a  = *(const float4*)(smem + embOff(c[0], j));
                    float4 b  = *(const float4*)(smem + embOff(c[1], j));
                    float4 cc = *(const float4*)(smem + embOff(c[2], j));
                    float4 dd = *(const float4*)(smem + embOff(c[3], j));
                    float u;
                    u = xv.x - a.x;  d0 = fmaf(u, u, d0);
                    u = xv.y - a.y;  d0 = fmaf(u, u, d0);
                    u = xv.z - a.z;  d0 = fmaf(u, u, d0);
                    u = xv.w - a.w;  d0 = fmaf(u, u, d0);
                    u = xv.x - b.x;  d1 = fmaf(u, u, d1);
                    u = xv.y - b.y;  d1 = fmaf(u, u, d1);
                    u = xv.z - b.z;  d1 = fmaf(u, u, d1);
                    u = xv.w - b.w;  d1 = fmaf(u, u, d1);
                    u = xv.x - cc.x; d2 = fmaf(u, u, d2);
                    u = xv.y - cc.y; d2 = fmaf(u, u, d2);
                    u = xv.z - cc.z; d2 = fmaf(u, u, d2);
                    u = xv.w - cc.w; d2 = fmaf(u, u, d2);
                    u = xv.x - dd.x; d3 = fmaf(u, u, d3);
                    u = xv.y - dd.y; d3 = fmaf(u, u, d3);
                    u = xv.z - dd.z; d3 = fmaf(u, u, d3);
                    u = xv.w - dd.w; d3 = fmaf(u, u, d3);
                }
                float dm = d0; int im = c[0];
                if (d1 < dm || (d1 == dm && c[1] < im)) { dm = d1; im = c[1]; }
                if (d2 < dm || (d2 == dm && c[2] < im)) { dm = d2; im = c[2]; }
                if (d3 < dm || (d3 == dm && c[3] < im)) { dm = d3; im = c[3]; }
                float do_ = __shfl_xor_sync(0xFFFFFFFFu, dm, 1);
                int   io_ = __shfl_xor_sync(0xFFFFFFFFu, im, 1);
                if (half == 0) {
                    int win = (do_ < dm || (do_ == dm && io_ < im)) ? io_ : im;
                    ((int*)(smem + SMEM_WIN))[row] = win;
                    if (out_size >= NROWS * DDIM + NROWS) {
                        out[(size_t)NROWS * DDIM + g] = (float)win;
                    }
                }
            }
        }
        __syncthreads();

        // ---- Gather quantized rows from smem emb (8 threads/row, 32B each) ----
        if (out_size >= NROWS * DDIM) {
#pragma unroll
            for (int sweep = 0; sweep < 4; sweep++) {
                int r = sweep * 96 + (tid >> 3);
                size_t gr = base + r;
                if (r < TILE_M && gr < (size_t)NROWS) {
                    int w = ((const int*)(smem + SMEM_WIN))[r];
                    int jj = (tid & 7) * 2;
                    float4 v0 = *(const float4*)(smem + embOff(w, jj));
                    float4 v1 = *(const float4*)(smem + embOff(w, jj + 1));
                    float4* q = (float4*)(out + gr * DDIM) + jj;
                    q[0] = v0; q[1] = v1;
                }
            }
        }
        __syncthreads();   // protect IDX/WIN before next tile
    }
}

extern "C" void kernel_launch(void* const* d_in, const int* in_sizes, int n_in,
                              void* d_out, int out_size) {
    const float* x   = (const float*)d_in[0];
    const float* emb = (const float*)d_in[1];
    float* out = (float*)d_out;
    cudaFuncSetAttribute(vq_kernel, cudaFuncAttributeMaxDynamicSharedMemorySize, SMEM_TOTAL);
    vq_kernel<<<148, NTHREADS, SMEM_TOTAL>>>(x, emb, out, out_size);
}